// round 7
// baseline (speedup 1.0000x reference)
#include <cuda_runtime.h>
#include <math.h>

#define NV      12288
#define NFEAT   128
#define NHID    64
#define NCLASS  16
#define MAXDEG  128

#define EX_U       8
#define EX_T       256
#define NCHUNKS    ((size_t)NV * NV / 4)                 // 37,748,736 uint4
#define EX_BLOCKS  (NCHUNKS / (EX_U * EX_T))             // 18,432 (exact)

// ---------------- device scratch (allocation-free) ----------------
__device__ int   g_cnt [NV];                    // neighbor count (excl. self)
__device__ int   g_cols[(size_t)NV * MAXDEG];   // neighbor col indices per row
__device__ float g_dinv[NV];                    // (deg+1)^-1/2
__device__ float g_Z1  [(size_t)NV * NHID];     // d ⊙ (x @ W1)
__device__ float g_Z2  [(size_t)NV * NCLASS];   // d ⊙ (H1 @ W2)

// ---------------- K0: zero counters (graph replays) ----------------
__global__ void k0_zero() {
    int i = blockIdx.x * blockDim.x + threadIdx.x;
    if (i < NV) g_cnt[i] = 0;
}

// =================================================================
// K1: flat streaming extract (8 LDG.128/thread, evict-first).
// =================================================================
__global__ void __launch_bounds__(EX_T) k1_extract(const uint4* __restrict__ adj) {
    const unsigned base = blockIdx.x * (EX_U * EX_T) + threadIdx.x;

    uint4 v[EX_U];
    #pragma unroll
    for (int u = 0; u < EX_U; u++)
        v[u] = __ldcs(&adj[(size_t)base + u * EX_T]);   // streaming, MLP=8

    #pragma unroll
    for (int u = 0; u < EX_U; u++) {
        unsigned m = (v[u].x | v[u].y) | (v[u].z | v[u].w);
        if (m) {                                        // ~0.8% of chunks
            unsigned idx4 = base + u * EX_T;
            unsigned row  = idx4 / (NV / 4);
            unsigned col0 = (idx4 - row * (NV / 4)) << 2;
            int* mycols = g_cols + (size_t)row * MAXDEG;
            if (v[u].x) { int p = atomicAdd(&g_cnt[row], 1); if (p < MAXDEG) mycols[p] = col0 + 0; }
            if (v[u].y) { int p = atomicAdd(&g_cnt[row], 1); if (p < MAXDEG) mycols[p] = col0 + 1; }
            if (v[u].z) { int p = atomicAdd(&g_cnt[row], 1); if (p < MAXDEG) mycols[p] = col0 + 2; }
            if (v[u].w) { int p = atomicAdd(&g_cnt[row], 1); if (p < MAXDEG) mycols[p] = col0 + 3; }
        }
    }
}

// =================================================================
// K2: Z1 = dinv ⊙ (x @ W1); materialize g_dinv.
// 256 thr = 16 rows x 16 col-quads (float4 accumulators, LDS.128 on W1).
// =================================================================
__global__ void __launch_bounds__(256) k2_xw1(const float* __restrict__ x,
                                              const float* __restrict__ W1) {
    __shared__ float4 sW[NFEAT * (NHID / 4)];   // 32 KB, row-major float4
    __shared__ float  sx[16][NFEAT];            // 8 KB
    const int row0 = blockIdx.x * 16;

    {
        const float4* Wv = reinterpret_cast<const float4*>(W1);
        #pragma unroll
        for (int i = 0; i < (NFEAT * NHID / 4) / 256; i++)
            sW[threadIdx.x + i * 256] = Wv[threadIdx.x + i * 256];
        const float4* xv = reinterpret_cast<const float4*>(x + (size_t)row0 * NFEAT);
        float4* sxv = reinterpret_cast<float4*>(&sx[0][0]);
        #pragma unroll
        for (int i = 0; i < (16 * NFEAT / 4) / 256; i++)
            sxv[threadIdx.x + i * 256] = xv[threadIdx.x + i * 256];
    }
    __syncthreads();

    const int r = threadIdx.x >> 4;             // row 0..15
    const int q = threadIdx.x & 15;             // col-quad 0..15
    const int row = row0 + r;
    const float di = rsqrtf((float)g_cnt[row] + 1.0f);
    if (q == 0) g_dinv[row] = di;

    float4 acc = make_float4(0.f, 0.f, 0.f, 0.f);
    #pragma unroll
    for (int f = 0; f < NFEAT; f++) {
        const float  xv = sx[r][f];
        const float4 w  = sW[f * (NHID / 4) + q];
        acc.x = fmaf(xv, w.x, acc.x);
        acc.y = fmaf(xv, w.y, acc.y);
        acc.z = fmaf(xv, w.z, acc.z);
        acc.w = fmaf(xv, w.w, acc.w);
    }
    acc.x *= di; acc.y *= di; acc.z *= di; acc.w *= di;
    reinterpret_cast<float4*>(g_Z1)[(size_t)row * (NHID / 4) + q] = acc;
}

// =================================================================
// K3: gather layer 1 (float4) + relu, fused @W2 -> Z2 = d ⊙ (H1 @ W2).
// 256 thr = 16 rows x 16 feat-quads; grid 768.
// =================================================================
__global__ void __launch_bounds__(256) k3_spmm1_hw2(const float* __restrict__ W2) {
    __shared__ float sW2[NHID * NCLASS];        // 4 KB
    __shared__ float sh[16][68];                // padded: no 2-way row conflict

    for (int i = threadIdx.x; i < NHID * NCLASS; i += 256) sW2[i] = W2[i];

    const int g = threadIdx.x >> 4;             // row 0..15
    const int t = threadIdx.x & 15;             // feat-quad 0..15
    const int row = blockIdx.x * 16 + g;
    int cnt = g_cnt[row]; if (cnt > MAXDEG) cnt = MAXDEG;
    const int* cols = g_cols + (size_t)row * MAXDEG;
    const float di = g_dinv[row];
    const float4* Z1v = reinterpret_cast<const float4*>(g_Z1);

    float4 acc = Z1v[(size_t)row * 16 + t];     // self loop
    int e = 0;
    for (; e + 4 <= cnt; e += 4) {
        int j0 = cols[e], j1 = cols[e+1], j2 = cols[e+2], j3 = cols[e+3];
        float4 a0 = Z1v[(size_t)j0 * 16 + t];
        float4 a1 = Z1v[(size_t)j1 * 16 + t];
        float4 a2 = Z1v[(size_t)j2 * 16 + t];
        float4 a3 = Z1v[(size_t)j3 * 16 + t];
        acc.x += (a0.x + a1.x) + (a2.x + a3.x);
        acc.y += (a0.y + a1.y) + (a2.y + a3.y);
        acc.z += (a0.z + a1.z) + (a2.z + a3.z);
        acc.w += (a0.w + a1.w) + (a2.w + a3.w);
    }
    for (; e < cnt; e++) {
        float4 a = Z1v[(size_t)cols[e] * 16 + t];
        acc.x += a.x; acc.y += a.y; acc.z += a.z; acc.w += a.w;
    }
    sh[g][4*t+0] = fmaxf(acc.x * di, 0.0f);
    sh[g][4*t+1] = fmaxf(acc.y * di, 0.0f);
    sh[g][4*t+2] = fmaxf(acc.z * di, 0.0f);
    sh[g][4*t+3] = fmaxf(acc.w * di, 0.0f);
    __syncthreads();

    // 16 rows x 16 classes; dot over 64 hidden feats from smem
    const int r = threadIdx.x >> 4;
    const int c = threadIdx.x & 15;
    float acc2 = 0.0f;
    #pragma unroll
    for (int f = 0; f < NHID; f++)
        acc2 = fmaf(sh[r][f], sW2[f * NCLASS + c], acc2);
    g_Z2[(size_t)row * NCLASS + c] = acc2 * di;  // row==blockIdx*16+r (r==g)
}

// =================================================================
// K4: gather layer 2 (float4) + relu + log_softmax -> out.
// 256 thr = 64 rows x 4 class-quads; grid 192.
// =================================================================
__global__ void __launch_bounds__(256) k4_spmm2_out(float4* __restrict__ out) {
    const int g = threadIdx.x >> 2;             // row 0..63
    const int t = threadIdx.x & 3;              // class-quad 0..3
    const int row = blockIdx.x * 64 + g;
    int cnt = g_cnt[row]; if (cnt > MAXDEG) cnt = MAXDEG;
    const int* cols = g_cols + (size_t)row * MAXDEG;
    const float4* Z2v = reinterpret_cast<const float4*>(g_Z2);

    float4 acc = Z2v[(size_t)row * 4 + t];      // self loop
    int e = 0;
    for (; e + 4 <= cnt; e += 4) {
        int j0 = cols[e], j1 = cols[e+1], j2 = cols[e+2], j3 = cols[e+3];
        float4 a0 = Z2v[(size_t)j0 * 4 + t];
        float4 a1 = Z2v[(size_t)j1 * 4 + t];
        float4 a2 = Z2v[(size_t)j2 * 4 + t];
        float4 a3 = Z2v[(size_t)j3 * 4 + t];
        acc.x += (a0.x + a1.x) + (a2.x + a3.x);
        acc.y += (a0.y + a1.y) + (a2.y + a3.y);
        acc.z += (a0.z + a1.z) + (a2.z + a3.z);
        acc.w += (a0.w + a1.w) + (a2.w + a3.w);
    }
    for (; e < cnt; e++) {
        float4 a = Z2v[(size_t)cols[e] * 4 + t];
        acc.x += a.x; acc.y += a.y; acc.z += a.z; acc.w += a.w;
    }
    const float di = g_dinv[row];
    float4 h;
    h.x = fmaxf(acc.x * di, 0.0f);
    h.y = fmaxf(acc.y * di, 0.0f);
    h.z = fmaxf(acc.z * di, 0.0f);
    h.w = fmaxf(acc.w * di, 0.0f);

    // log_softmax over 16 classes = 4 locals x 4 lanes (xor 1,2 in-group)
    float m = fmaxf(fmaxf(h.x, h.y), fmaxf(h.z, h.w));
    m = fmaxf(m, __shfl_xor_sync(0xffffffffu, m, 1));
    m = fmaxf(m, __shfl_xor_sync(0xffffffffu, m, 2));
    float s = expf(h.x - m) + expf(h.y - m) + expf(h.z - m) + expf(h.w - m);
    s += __shfl_xor_sync(0xffffffffu, s, 1);
    s += __shfl_xor_sync(0xffffffffu, s, 2);
    const float lse = m + logf(s);
    out[(size_t)row * 4 + t] = make_float4(h.x - lse, h.y - lse, h.z - lse, h.w - lse);
}

// ---------------- launch ----------------
extern "C" void kernel_launch(void* const* d_in, const int* in_sizes, int n_in,
                              void* d_out, int out_size) {
    const float *x = nullptr, *adj = nullptr, *W1 = nullptr, *W2 = nullptr;
    for (int i = 0; i < n_in; i++) {
        long s = (long)in_sizes[i];
        if      (s == (long)NV * NV)       adj = (const float*)d_in[i];
        else if (s == (long)NV * NFEAT)    x   = (const float*)d_in[i];
        else if (s == (long)NFEAT * NHID)  W1  = (const float*)d_in[i];
        else if (s == (long)NHID * NCLASS) W2  = (const float*)d_in[i];
    }

    k0_zero      <<<(NV + 1023) / 1024, 1024>>>();
    k1_extract   <<<EX_BLOCKS, EX_T>>>((const uint4*)adj);
    k2_xw1       <<<NV / 16,   256>>>(x, W1);
    k3_spmm1_hw2 <<<NV / 16,   256>>>(W2);
    k4_spmm2_out <<<NV / 64,   256>>>((float4*)d_out);
}

// round 12
// speedup vs baseline: 1.1514x; 1.1514x over previous
#include <cuda_runtime.h>
#include <math.h>

#define NV      12288
#define NFEAT   128
#define NHID    64
#define NCLASS  16
#define MAXDEG  128

#define EX_U       8
#define EX_T       256
#define NCHUNKS    ((size_t)NV * NV / 4)                 // 37,748,736 uint4
#define EX_BLOCKS  (NCHUNKS / (EX_U * EX_T))             // 18,432 (exact)

#define XW1_ROWS   16
#define XW1_BLOCKS (NV / XW1_ROWS)                       // 768

// ---------------- device scratch (allocation-free) ----------------
// g_cnt is zero at process start (static init) and re-zeroed by k4 at the
// end of every call -> each call sees zeros without a dedicated kernel.
__device__ int   g_cnt [NV];
__device__ int   g_cols[(size_t)NV * MAXDEG];
__device__ float g_dinv[NV];
__device__ float g_Z1  [(size_t)NV * NHID];     // d ⊙ (x @ W1)
__device__ float g_Z2  [(size_t)NV * NCLASS];   // d ⊙ (H1 @ W2)

// =================================================================
// K1: flat streaming extract (8 LDG.128/thread). R4-exact (no __ldcs).
// =================================================================
__global__ void __launch_bounds__(EX_T) k1_extract(const uint4* __restrict__ adj) {
    const unsigned base = blockIdx.x * (EX_U * EX_T) + threadIdx.x;

    uint4 v[EX_U];
    #pragma unroll
    for (int u = 0; u < EX_U; u++)
        v[u] = adj[(size_t)base + u * EX_T];            // MLP = 8

    #pragma unroll
    for (int u = 0; u < EX_U; u++) {
        unsigned m = (v[u].x | v[u].y) | (v[u].z | v[u].w);
        if (m) {                                        // ~0.8% of chunks
            unsigned idx4 = base + u * EX_T;
            unsigned row  = idx4 / (NV / 4);
            unsigned col0 = (idx4 - row * (NV / 4)) << 2;
            int* mycols = g_cols + row * MAXDEG;
            if (v[u].x) { int p = atomicAdd(&g_cnt[row], 1); if (p < MAXDEG) mycols[p] = col0 + 0; }
            if (v[u].y) { int p = atomicAdd(&g_cnt[row], 1); if (p < MAXDEG) mycols[p] = col0 + 1; }
            if (v[u].z) { int p = atomicAdd(&g_cnt[row], 1); if (p < MAXDEG) mycols[p] = col0 + 2; }
            if (v[u].w) { int p = atomicAdd(&g_cnt[row], 1); if (p < MAXDEG) mycols[p] = col0 + 3; }
        }
    }
}

// =================================================================
// K2: Z1 = dinv ⊙ (x @ W1); materialize g_dinv. (R4-exact)
// =================================================================
__global__ void __launch_bounds__(256) k2_xw1(const float* __restrict__ x,
                                              const float* __restrict__ W1) {
    __shared__ float sW[NFEAT * NHID];       // 32 KB
    __shared__ float sx[XW1_ROWS][NFEAT];    // 8 KB
    const int row0 = blockIdx.x * XW1_ROWS;

    {
        const float4* Wv = reinterpret_cast<const float4*>(W1);
        float4* sWv = reinterpret_cast<float4*>(sW);
        #pragma unroll
        for (int i = 0; i < (NFEAT * NHID / 4) / 256; i++)
            sWv[threadIdx.x + i * 256] = Wv[threadIdx.x + i * 256];
        const float4* xv = reinterpret_cast<const float4*>(x + (size_t)row0 * NFEAT);
        float4* sxv = reinterpret_cast<float4*>(&sx[0][0]);
        #pragma unroll
        for (int i = 0; i < (XW1_ROWS * NFEAT / 4) / 256; i++)
            sxv[threadIdx.x + i * 256] = xv[threadIdx.x + i * 256];
    }
    __syncthreads();

    const int k  = threadIdx.x & 63;
    const int rl = threadIdx.x >> 6;                    // 0..3
    #pragma unroll
    for (int g = 0; g < 4; g++) {
        const int r   = g * 4 + rl;
        const int row = row0 + r;
        const float di = rsqrtf((float)g_cnt[row] + 1.0f);
        if (k == 0) g_dinv[row] = di;
        float acc = 0.0f;
        #pragma unroll
        for (int f = 0; f < NFEAT; f++)
            acc = fmaf(sx[r][f], sW[f * NHID + k], acc);
        g_Z1[row * NHID + k] = acc * di;
    }
}

// =================================================================
// K3: gather L1 + relu, fused @W2 -> Z2 = d ⊙ (H1 @ W2).
// 4 rows x 64 feats per block; unroll 8, 4 independent accumulators,
// 32-bit addressing throughout.
// =================================================================
__global__ void __launch_bounds__(256) k3_spmm1_hw2(const float* __restrict__ W2) {
    __shared__ float sW2[NHID * NCLASS];     // 4 KB
    __shared__ float sh[4][NHID];
    __shared__ float sp[4][4][NCLASS];

    for (int i = threadIdx.x; i < NHID * NCLASS; i += 256) sW2[i] = W2[i];

    const int r   = threadIdx.x >> 6;
    const int k   = threadIdx.x & 63;
    const int row = blockIdx.x * 4 + r;
    int cnt = g_cnt[row]; if (cnt > MAXDEG) cnt = MAXDEG;
    const int* __restrict__ cols = g_cols + row * MAXDEG;
    const float di = g_dinv[row];
    const float* __restrict__ Z1 = g_Z1;

    float a0 = Z1[row * NHID + k];                      // self loop
    float a1 = 0.f, a2 = 0.f, a3 = 0.f;
    int e = 0;
    for (; e + 8 <= cnt; e += 8) {
        int j0 = cols[e+0], j1 = cols[e+1], j2 = cols[e+2], j3 = cols[e+3];
        int j4 = cols[e+4], j5 = cols[e+5], j6 = cols[e+6], j7 = cols[e+7];
        float t0 = Z1[j0 * NHID + k];
        float t1 = Z1[j1 * NHID + k];
        float t2 = Z1[j2 * NHID + k];
        float t3 = Z1[j3 * NHID + k];
        float t4 = Z1[j4 * NHID + k];
        float t5 = Z1[j5 * NHID + k];
        float t6 = Z1[j6 * NHID + k];
        float t7 = Z1[j7 * NHID + k];
        a0 += t0; a1 += t1; a2 += t2; a3 += t3;
        a0 += t4; a1 += t5; a2 += t6; a3 += t7;
    }
    if (e + 4 <= cnt) {
        int j0 = cols[e+0], j1 = cols[e+1], j2 = cols[e+2], j3 = cols[e+3];
        a0 += Z1[j0 * NHID + k];
        a1 += Z1[j1 * NHID + k];
        a2 += Z1[j2 * NHID + k];
        a3 += Z1[j3 * NHID + k];
        e += 4;
    }
    for (; e < cnt; e++)
        a0 += Z1[cols[e] * NHID + k];
    float acc = (a0 + a1) + (a2 + a3);
    sh[r][k] = fmaxf(acc * di, 0.0f);                   // H1[row][k]
    __syncthreads();

    // H1[row] @ W2 : 16 classes x 4 partials of 16 feats
    const int c = threadIdx.x & 15;
    const int p = (threadIdx.x >> 4) & 3;
    float part = 0.0f;
    #pragma unroll
    for (int f = 0; f < 16; f++)
        part = fmaf(sh[r][p * 16 + f], sW2[(p * 16 + f) * NCLASS + c], part);
    sp[r][p][c] = part;
    __syncthreads();

    if (p == 0) {
        float val = (sp[r][0][c] + sp[r][1][c]) + (sp[r][2][c] + sp[r][3][c]);
        g_Z2[row * NCLASS + c] = val * di;
    }
}

// =================================================================
// K4: gather L2 + relu + log_softmax -> out; re-zeroes g_cnt[row].
// 8 rows x 16 classes per block; unroll 8, 4 accumulators.
// =================================================================
__global__ void __launch_bounds__(128) k4_spmm2_out(float* __restrict__ out) {
    const int row = blockIdx.x * 8 + (threadIdx.x >> 4);
    const int c   = threadIdx.x & 15;
    int cnt = g_cnt[row]; if (cnt > MAXDEG) cnt = MAXDEG;
    const int* __restrict__ cols = g_cols + row * MAXDEG;
    const float* __restrict__ Z2 = g_Z2;

    float a0 = Z2[row * NCLASS + c];                    // self loop
    float a1 = 0.f, a2 = 0.f, a3 = 0.f;
    int e = 0;
    for (; e + 8 <= cnt; e += 8) {
        int j0 = cols[e+0], j1 = cols[e+1], j2 = cols[e+2], j3 = cols[e+3];
        int j4 = cols[e+4], j5 = cols[e+5], j6 = cols[e+6], j7 = cols[e+7];
        float t0 = Z2[j0 * NCLASS + c];
        float t1 = Z2[j1 * NCLASS + c];
        float t2 = Z2[j2 * NCLASS + c];
        float t3 = Z2[j3 * NCLASS + c];
        float t4 = Z2[j4 * NCLASS + c];
        float t5 = Z2[j5 * NCLASS + c];
        float t6 = Z2[j6 * NCLASS + c];
        float t7 = Z2[j7 * NCLASS + c];
        a0 += t0; a1 += t1; a2 += t2; a3 += t3;
        a0 += t4; a1 += t5; a2 += t6; a3 += t7;
    }
    if (e + 4 <= cnt) {
        int j0 = cols[e+0], j1 = cols[e+1], j2 = cols[e+2], j3 = cols[e+3];
        a0 += Z2[j0 * NCLASS + c];
        a1 += Z2[j1 * NCLASS + c];
        a2 += Z2[j2 * NCLASS + c];
        a3 += Z2[j3 * NCLASS + c];
        e += 4;
    }
    for (; e < cnt; e++)
        a0 += Z2[cols[e] * NCLASS + c];
    float h = fmaxf(((a0 + a1) + (a2 + a3)) * g_dinv[row], 0.0f);

    // log_softmax over the 16-lane group
    float m = h;
    #pragma unroll
    for (int o = 8; o >= 1; o >>= 1)
        m = fmaxf(m, __shfl_xor_sync(0xffffffffu, m, o));
    float ex = expf(h - m);
    float s = ex;
    #pragma unroll
    for (int o = 8; o >= 1; o >>= 1)
        s += __shfl_xor_sync(0xffffffffu, s, o);
    out[row * NCLASS + c] = (h - m) - logf(s);

    // self-clean: next call's k1 needs zeroed counters (this is the last reader)
    if (c == 0) g_cnt[row] = 0;
}

// ---------------- launch ----------------
extern "C" void kernel_launch(void* const* d_in, const int* in_sizes, int n_in,
                              void* d_out, int out_size) {
    const float *x = nullptr, *adj = nullptr, *W1 = nullptr, *W2 = nullptr;
    for (int i = 0; i < n_in; i++) {
        long s = (long)in_sizes[i];
        if      (s == (long)NV * NV)       adj = (const float*)d_in[i];
        else if (s == (long)NV * NFEAT)    x   = (const float*)d_in[i];
        else if (s == (long)NFEAT * NHID)  W1  = (const float*)d_in[i];
        else if (s == (long)NHID * NCLASS) W2  = (const float*)d_in[i];
    }
    float* out = (float*)d_out;

    k1_extract   <<<EX_BLOCKS,  EX_T>>>((const uint4*)adj);
    k2_xw1       <<<XW1_BLOCKS, 256>>>(x, W1);
    k3_spmm1_hw2 <<<NV / 4,     256>>>(W2);
    k4_spmm2_out <<<NV / 8,     128>>>(out);
}